// round 8
// baseline (speedup 1.0000x reference)
#include <cuda_runtime.h>
#include <cstdint>

#define BB 8
#define NN 4096
#define QUART 1024
#define KK 16
#define THREADS 256
#define QPB 64           // queries per block
#define NG 4             // thread-groups (quarters) per query
#define SLOTSQ 32        // collect slots per quarter
#define FLTMAX 3.402823466e38f

// smem: xs,ys,zs (48KB) + si u16[NG*SLOTSQ][QPB] (16KB) + scnt (1KB) = 65KB
#define SMEM_BYTES ((3 * NN) * 4 + (NG * SLOTSQ * QPB) * 2 + THREADS * 4)

// ---------------- packed f32x2 helpers ----------------
__device__ __forceinline__ unsigned long long pk2(float v) {
    unsigned long long r;
    asm("mov.b64 %0, {%1, %1};" : "=l"(r) : "f"(v));
    return r;
}
__device__ __forceinline__ unsigned long long mul2_(unsigned long long a, unsigned long long b) {
    unsigned long long r;
    asm("mul.rn.f32x2 %0, %1, %2;" : "=l"(r) : "l"(a), "l"(b));
    return r;
}
__device__ __forceinline__ unsigned long long add2_(unsigned long long a, unsigned long long b) {
    unsigned long long r;
    asm("add.rn.f32x2 %0, %1, %2;" : "=l"(r) : "l"(a), "l"(b));
    return r;
}
__device__ __forceinline__ unsigned long long fma2_(unsigned long long a, unsigned long long b,
                                                    unsigned long long c) {
    unsigned long long r;
    asm("fma.rn.f32x2 %0, %1, %2, %3;" : "=l"(r) : "l"(a), "l"(b), "l"(c));
    return r;
}
__device__ __forceinline__ void unpk2(unsigned long long v, float& lo, float& hi) {
    asm("mov.b64 {%0, %1}, %2;" : "=f"(lo), "=f"(hi) : "l"(v));
}

// Packed distance, norm recomputed inline (R3-proven formula; same rel_err/indices):
//   sm = fmaf(x,x, fmaf(y,y, z*z)); in = fmaf(z,zq, fmaf(y,yq, x*xq)); d = fmaf(-2,in, sq+sm)
__device__ __forceinline__ unsigned long long dist2(
    unsigned long long x2, unsigned long long y2, unsigned long long z2,
    unsigned long long xq2, unsigned long long yq2, unsigned long long zq2,
    unsigned long long sq2, unsigned long long n2) {
    unsigned long long sm = fma2_(x2, x2, fma2_(y2, y2, mul2_(z2, z2)));
    unsigned long long in = fma2_(z2, zq2, fma2_(y2, yq2, mul2_(x2, xq2)));
    return fma2_(n2, in, add2_(sq2, sm));
}

// Scalar distance, bitwise-identical to dist2 lanes (.rn IEEE both paths).
__device__ __forceinline__ float dists(float x, float y, float z,
                                       float xq, float yq, float zq, float sq) {
    float sm = fmaf(x, x, fmaf(y, y, z * z));
    float in = fmaf(z, zq, fmaf(y, yq, x * xq));
    return fmaf(-2.0f, in, sq + sm);
}

// Values-only sorted-16 insert (branch-free min/max shift)
__device__ __forceinline__ void insert16(float v[16], float d) {
#pragma unroll
    for (int j = 15; j >= 1; --j)
        v[j] = fminf(v[j], fmaxf(v[j - 1], d));
    v[0] = fminf(v[0], d);
}

// (d, idx) lexicographic pair-insert into sorted 16-list (lax.top_k order)
__device__ __forceinline__ void pins(float rd[16], int ri[16], float d, int i) {
    bool lessLast = (d < rd[15]) || (d == rd[15] && i < ri[15]);
    if (!lessLast) return;
#pragma unroll
    for (int j = 15; j >= 1; --j) {
        bool le = (d < rd[j - 1]) || (d == rd[j - 1] && i < ri[j - 1]);
        bool lj = (d < rd[j]) || (d == rd[j] && i < ri[j]);
        rd[j] = le ? rd[j - 1] : (lj ? d : rd[j]);
        ri[j] = le ? ri[j - 1] : (lj ? i : ri[j]);
    }
    bool l0 = (d < rd[0]) || (d == rd[0] && i < ri[0]);
    if (l0) { rd[0] = d; ri[0] = i; }
}

extern __shared__ char smem_raw[];

__global__ void __launch_bounds__(THREADS, 3)
knn_edge_kernel(const float* __restrict__ cloud, float* __restrict__ out) {
    float* xs = (float*)smem_raw;
    float* ys = xs + NN;
    float* zs = ys + NN;
    unsigned short* si = (unsigned short*)(zs + NN);   // [NG*SLOTSQ][QPB]
    int* scnt = (int*)(si + NG * SLOTSQ * QPB);        // [THREADS]

    const int tid = threadIdx.x;
    const int qt  = tid & (QPB - 1);   // query column 0..63
    const int g   = tid >> 6;          // quarter 0..3
    const int b    = blockIdx.x >> 6;  // 64 tiles per batch
    const int tile = blockIdx.x & 63;
    const int q    = tile * QPB + qt;

    // ---- Load batch cloud to SMEM (SoA xyz) ----
    const float4* cb4 = (const float4*)(cloud + (size_t)b * 3 * NN);
    float4* xs4 = (float4*)xs; float4* ys4 = (float4*)ys; float4* zs4 = (float4*)zs;
    for (int i = tid; i < NN / 4; i += THREADS) {
        xs4[i] = cb4[i];
        ys4[i] = cb4[NN / 4 + i];
        zs4[i] = cb4[2 * (NN / 4) + i];
    }
    __syncthreads();

    const float xq = xs[q], yq = ys[q], zq = zs[q];
    const float sq = fmaf(xq, xq, fmaf(yq, yq, zq * zq));
    const unsigned long long xq2 = pk2(xq), yq2 = pk2(yq), zq2 = pk2(zq);
    const unsigned long long sq2 = pk2(sq), n2 = pk2(-2.0f);

    const ulonglong2* xs2 = (const ulonglong2*)xs;
    const ulonglong2* ys2 = (const ulonglong2*)ys;
    const ulonglong2* zs2 = (const ulonglong2*)zs;

    const int mstart = g * QUART;

    // ---- Pass 1: branch-free 16-bucket depth-2 min sketch over this quarter ----
    float m1[16], m2[16];
#pragma unroll
    for (int t = 0; t < 16; ++t) { m1[t] = FLTMAX; m2[t] = FLTMAX; }

#pragma unroll 1
    for (int it = 0; it < QUART / 16; ++it) {
        const int p0 = (mstart >> 2) + it * 4;
#pragma unroll
        for (int j = 0; j < 4; ++j) {
            ulonglong2 X = xs2[p0 + j], Y = ys2[p0 + j], Z = zs2[p0 + j];
            float d0, d1, d2v, d3;
            unpk2(dist2(X.x, Y.x, Z.x, xq2, yq2, zq2, sq2, n2), d0, d1);
            unpk2(dist2(X.y, Y.y, Z.y, xq2, yq2, zq2, sq2, n2), d2v, d3);
            const int t0 = j * 4;
            m2[t0 + 0] = fminf(m2[t0 + 0], fmaxf(m1[t0 + 0], d0)); m1[t0 + 0] = fminf(m1[t0 + 0], d0);
            m2[t0 + 1] = fminf(m2[t0 + 1], fmaxf(m1[t0 + 1], d1)); m1[t0 + 1] = fminf(m1[t0 + 1], d1);
            m2[t0 + 2] = fminf(m2[t0 + 2], fmaxf(m1[t0 + 2], d2v)); m1[t0 + 2] = fminf(m1[t0 + 2], d2v);
            m2[t0 + 3] = fminf(m2[t0 + 3], fmaxf(m1[t0 + 3], d3)); m1[t0 + 3] = fminf(m1[t0 + 3], d3);
        }
    }

    // T = 16th smallest of the 32 sketch values (subset order stat => T >= exact local d16)
    float v[16];
#pragma unroll
    for (int t = 0; t < 16; ++t) v[t] = FLTMAX;
#pragma unroll
    for (int t = 0; t < 16; ++t) { insert16(v, m1[t]); insert16(v, m2[t]); }
    const float T = v[15];

    // ---- Pass 2: collect indices of all d <= T (R5-proven predicated form) ----
    const int rowbase = g * SLOTSQ;
    int cnt = 0;
#pragma unroll 1
    for (int it = 0; it < QUART / 16; ++it) {
        const int c0 = mstart + it * 16;
        const int p0 = c0 >> 2;
#pragma unroll
        for (int j = 0; j < 4; ++j) {
            ulonglong2 X = xs2[p0 + j], Y = ys2[p0 + j], Z = zs2[p0 + j];
            float dd[4];
            unpk2(dist2(X.x, Y.x, Z.x, xq2, yq2, zq2, sq2, n2), dd[0], dd[1]);
            unpk2(dist2(X.y, Y.y, Z.y, xq2, yq2, zq2, sq2, n2), dd[2], dd[3]);
#pragma unroll
            for (int k = 0; k < 4; ++k) {
                bool pr = (dd[k] <= T) && (cnt < SLOTSQ);
                if (pr) si[(rowbase + cnt) * QPB + qt] = (unsigned short)(c0 + j * 4 + k);
                cnt += pr;
            }
        }
    }

    // ---- Overflow fallback (rare): exact top-16 rescan of this quarter ----
    if (cnt >= SLOTSQ) {
        float rdF[16]; int riF[16];
#pragma unroll
        for (int t = 0; t < 16; ++t) { rdF[t] = FLTMAX; riF[t] = 0; }
        for (int mm = mstart; mm < mstart + QUART; ++mm) {
            float d = dists(xs[mm], ys[mm], zs[mm], xq, yq, zq, sq);
            pins(rdF, riF, d, mm);
        }
#pragma unroll
        for (int t = 0; t < 16; ++t)
            si[(rowbase + t) * QPB + qt] = (unsigned short)riF[t];
        cnt = 16;
    }
    scnt[tid] = cnt;
    __syncthreads();

    // ---- Exact selection over all 4 quarters' survivors (threads 0..63) ----
    if (tid < QPB) {
        float rd[16]; int ri[16];
#pragma unroll
        for (int t = 0; t < 16; ++t) { rd[t] = FLTMAX; ri[t] = 0; }
#pragma unroll 1
        for (int gg = 0; gg < NG; ++gg) {
            const int c = scnt[gg * QPB + tid];
            for (int s = 0; s < c; ++s) {
                int ii = (int)si[(gg * SLOTSQ + s) * QPB + tid];
                float d = dists(xs[ii], ys[ii], zs[ii], xq, yq, zq, sq);
                pins(rd, ri, d, ii);
            }
        }
        // publish sorted indices for the gather groups
#pragma unroll
        for (int t = 0; t < 16; ++t)
            si[t * QPB + tid] = (unsigned short)ri[t];
    }
    __syncthreads();

    // ---- Emit edge features out[b][c][q][k]; one channel pair per group ----
    const size_t base = (((size_t)b * 6) * NN + q) * KK;
    if (g == 0) {
        // central channels 0..2 (no gather needed)
        float cvals[3] = {xq, yq, zq};
#pragma unroll
        for (int c = 0; c < 3; ++c) {
            float4 vv = make_float4(cvals[c], cvals[c], cvals[c], cvals[c]);
            float4* op = (float4*)(out + base + (size_t)c * NN * KK);
            op[0] = vv; op[1] = vv; op[2] = vv; op[3] = vv;
        }
    } else {
        int rr[16];
#pragma unroll
        for (int k = 0; k < 16; ++k) rr[k] = (int)si[k * QPB + qt];
        const float* arr = (g == 1) ? xs : (g == 2) ? ys : zs;
        const float qv   = (g == 1) ? xq : (g == 2) ? yq : zq;
        float nv[16];
#pragma unroll
        for (int k = 0; k < 16; ++k) nv[k] = arr[rr[k]] - qv;
        float4* op = (float4*)(out + base + (size_t)(2 + g) * NN * KK);
        op[0] = make_float4(nv[0], nv[1], nv[2], nv[3]);
        op[1] = make_float4(nv[4], nv[5], nv[6], nv[7]);
        op[2] = make_float4(nv[8], nv[9], nv[10], nv[11]);
        op[3] = make_float4(nv[12], nv[13], nv[14], nv[15]);
    }
}

extern "C" void kernel_launch(void* const* d_in, const int* in_sizes, int n_in,
                              void* d_out, int out_size) {
    const float* cloud = (const float*)d_in[0];
    float* out = (float*)d_out;

    cudaFuncSetAttribute(knn_edge_kernel,
                         cudaFuncAttributeMaxDynamicSharedMemorySize, SMEM_BYTES);

    dim3 grid(BB * (NN / QPB));   // 8 * 64 = 512 blocks
    dim3 block(THREADS);
    knn_edge_kernel<<<grid, block, SMEM_BYTES>>>(cloud, out);
}

// round 9
// speedup vs baseline: 2.0094x; 2.0094x over previous
#include <cuda_runtime.h>
#include <cstdint>

#define BB 8
#define NN 4096
#define HALF 2048
#define KK 16
#define THREADS 256
#define QPB 128          // queries per block
#define SLOTSH 35        // survivor capacity before fallback (clamp row)
#define ROWSH 40         // physical rows per half (pads absorb pre-clamp overshoot)
#define FLTMAX 3.402823466e38f

// smem: xs,ys,zs,ss (64KB) + si u16[2*ROWSH][128] (20KB) + scnt (1KB)
#define SMEM_BYTES ((4 * NN) * 4 + (2 * ROWSH * QPB) * 2 + THREADS * 4)

// ---------------- packed f32x2 helpers ----------------
__device__ __forceinline__ unsigned long long pk2(float v) {
    unsigned long long r;
    asm("mov.b64 %0, {%1, %1};" : "=l"(r) : "f"(v));
    return r;
}
__device__ __forceinline__ unsigned long long mul2_(unsigned long long a, unsigned long long b) {
    unsigned long long r;
    asm("mul.rn.f32x2 %0, %1, %2;" : "=l"(r) : "l"(a), "l"(b));
    return r;
}
__device__ __forceinline__ unsigned long long add2_(unsigned long long a, unsigned long long b) {
    unsigned long long r;
    asm("add.rn.f32x2 %0, %1, %2;" : "=l"(r) : "l"(a), "l"(b));
    return r;
}
__device__ __forceinline__ unsigned long long fma2_(unsigned long long a, unsigned long long b,
                                                    unsigned long long c) {
    unsigned long long r;
    asm("fma.rn.f32x2 %0, %1, %2, %3;" : "=l"(r) : "l"(a), "l"(b), "l"(c));
    return r;
}
__device__ __forceinline__ void unpk2(unsigned long long v, float& lo, float& hi) {
    asm("mov.b64 {%0, %1}, %2;" : "=f"(lo), "=f"(hi) : "l"(v));
}

// Packed distance with precomputed candidate norm s2:
//   in = fmaf(z,zq, fmaf(y,yq, x*xq));  d = fmaf(-2, in, sq + s)
__device__ __forceinline__ unsigned long long dist2p(
    unsigned long long x2, unsigned long long y2, unsigned long long z2, unsigned long long s2,
    unsigned long long xq2, unsigned long long yq2, unsigned long long zq2,
    unsigned long long sq2, unsigned long long n2) {
    unsigned long long in = fma2_(z2, zq2, fma2_(y2, yq2, mul2_(x2, xq2)));
    return fma2_(n2, in, add2_(sq2, s2));
}

// Scalar distance, bitwise-identical to dist2p lanes (.rn IEEE both paths).
__device__ __forceinline__ float dists(float x, float y, float z, float sm,
                                       float xq, float yq, float zq, float sq) {
    float in = fmaf(z, zq, fmaf(y, yq, x * xq));
    return fmaf(-2.0f, in, sq + sm);
}

// Values-only sorted-16 insert (branch-free min/max shift)
__device__ __forceinline__ void insert16(float v[16], float d) {
#pragma unroll
    for (int j = 15; j >= 1; --j)
        v[j] = fminf(v[j], fmaxf(v[j - 1], d));
    v[0] = fminf(v[0], d);
}

// (d, idx) lexicographic pair-insert into sorted 16-list (lax.top_k order)
__device__ __forceinline__ void pins(float rd[16], int ri[16], float d, int i) {
    bool lessLast = (d < rd[15]) || (d == rd[15] && i < ri[15]);
    if (!lessLast) return;
#pragma unroll
    for (int j = 15; j >= 1; --j) {
        bool le = (d < rd[j - 1]) || (d == rd[j - 1] && i < ri[j - 1]);
        bool lj = (d < rd[j]) || (d == rd[j] && i < ri[j]);
        rd[j] = le ? rd[j - 1] : (lj ? d : rd[j]);
        ri[j] = le ? ri[j - 1] : (lj ? i : ri[j]);
    }
    bool l0 = (d < rd[0]) || (d == rd[0] && i < ri[0]);
    if (l0) { rd[0] = d; ri[0] = i; }
}

extern __shared__ char smem_raw[];

__global__ void __launch_bounds__(THREADS, 2)
knn_edge_kernel(const float* __restrict__ cloud, float* __restrict__ out) {
    float* xs = (float*)smem_raw;
    float* ys = xs + NN;
    float* zs = ys + NN;
    float* ss = zs + NN;
    unsigned short* si = (unsigned short*)(ss + NN);   // [2*ROWSH][QPB]
    int* scnt = (int*)(si + 2 * ROWSH * QPB);          // [THREADS]

    const int tid = threadIdx.x;
    const int qc  = tid & (QPB - 1);
    const int h   = tid >> 7;          // half 0/1
    const int b    = blockIdx.x >> 5;
    const int tile = blockIdx.x & 31;
    const int q    = tile * QPB + qc;

    // ---- Load batch cloud to SMEM (SoA) + precompute norms ----
    const float4* cb4 = (const float4*)(cloud + (size_t)b * 3 * NN);
    float4* xs4 = (float4*)xs; float4* ys4 = (float4*)ys;
    float4* zs4 = (float4*)zs; float4* ss4 = (float4*)ss;
    for (int i = tid; i < NN / 4; i += THREADS) {
        xs4[i] = cb4[i];
        ys4[i] = cb4[NN / 4 + i];
        zs4[i] = cb4[2 * (NN / 4) + i];
    }
    __syncthreads();
    for (int i = tid; i < NN / 4; i += THREADS) {
        float4 X = xs4[i], Y = ys4[i], Z = zs4[i], S;
        S.x = fmaf(X.x, X.x, fmaf(Y.x, Y.x, Z.x * Z.x));
        S.y = fmaf(X.y, X.y, fmaf(Y.y, Y.y, Z.y * Z.y));
        S.z = fmaf(X.z, X.z, fmaf(Y.z, Y.z, Z.z * Z.z));
        S.w = fmaf(X.w, X.w, fmaf(Y.w, Y.w, Z.w * Z.w));
        ss4[i] = S;
    }
    __syncthreads();

    const float xq = xs[q], yq = ys[q], zq = zs[q], sq = ss[q];
    const unsigned long long xq2 = pk2(xq), yq2 = pk2(yq), zq2 = pk2(zq);
    const unsigned long long sq2 = pk2(sq), n2 = pk2(-2.0f);

    const ulonglong2* xs2 = (const ulonglong2*)xs;
    const ulonglong2* ys2 = (const ulonglong2*)ys;
    const ulonglong2* zs2 = (const ulonglong2*)zs;
    const ulonglong2* ss2 = (const ulonglong2*)ss;

    const int mstart = h * HALF;

    // ---- Pass 1: branch-free 16-bucket depth-2 min sketch over this half ----
    float m1[16], m2[16];
#pragma unroll
    for (int t = 0; t < 16; ++t) { m1[t] = FLTMAX; m2[t] = FLTMAX; }

#pragma unroll 1
    for (int it = 0; it < HALF / 16; ++it) {
        const int p0 = (mstart >> 2) + it * 4;
#pragma unroll
        for (int j = 0; j < 4; ++j) {
            ulonglong2 X = xs2[p0 + j], Y = ys2[p0 + j], Z = zs2[p0 + j], S = ss2[p0 + j];
            float d0, d1, d2v, d3;
            unpk2(dist2p(X.x, Y.x, Z.x, S.x, xq2, yq2, zq2, sq2, n2), d0, d1);
            unpk2(dist2p(X.y, Y.y, Z.y, S.y, xq2, yq2, zq2, sq2, n2), d2v, d3);
            const int t0 = j * 4;
            m2[t0 + 0] = fminf(m2[t0 + 0], fmaxf(m1[t0 + 0], d0)); m1[t0 + 0] = fminf(m1[t0 + 0], d0);
            m2[t0 + 1] = fminf(m2[t0 + 1], fmaxf(m1[t0 + 1], d1)); m1[t0 + 1] = fminf(m1[t0 + 1], d1);
            m2[t0 + 2] = fminf(m2[t0 + 2], fmaxf(m1[t0 + 2], d2v)); m1[t0 + 2] = fminf(m1[t0 + 2], d2v);
            m2[t0 + 3] = fminf(m2[t0 + 3], fmaxf(m1[t0 + 3], d3)); m1[t0 + 3] = fminf(m1[t0 + 3], d3);
        }
    }

    // T = 16th smallest of the 32 stored sketch values (>= exact d16 of this half)
    float v[16];
#pragma unroll
    for (int t = 0; t < 16; ++t) v[t] = FLTMAX;
#pragma unroll
    for (int t = 0; t < 16; ++t) { insert16(v, m1[t]); insert16(v, m2[t]); }
    const float T = v[15];

    // ---- Pass 2: collect indices of all d <= T via predicated offset walk ----
    // Per candidate: FSETP + predicated STS + predicated IADD; clamp once per 4.
    const int soff0 = (h * ROWSH) * QPB + qc;
    const int somax = soff0 + SLOTSH * QPB;      // clamp row; pads rows absorb overshoot
    int soff = soff0;
#pragma unroll 1
    for (int it = 0; it < HALF / 16; ++it) {
        const int c0 = mstart + it * 16;
        const int p0 = c0 >> 2;
#pragma unroll
        for (int j = 0; j < 4; ++j) {
            ulonglong2 X = xs2[p0 + j], Y = ys2[p0 + j], Z = zs2[p0 + j], S = ss2[p0 + j];
            float dd[4];
            unpk2(dist2p(X.x, Y.x, Z.x, S.x, xq2, yq2, zq2, sq2, n2), dd[0], dd[1]);
            unpk2(dist2p(X.y, Y.y, Z.y, S.y, xq2, yq2, zq2, sq2, n2), dd[2], dd[3]);
#pragma unroll
            for (int k = 0; k < 4; ++k) {
                bool pr = (dd[k] <= T);
                if (pr) si[soff] = (unsigned short)(c0 + j * 4 + k);
                if (pr) soff += QPB;
            }
            soff = (soff > somax) ? somax : soff;   // amortized clamp (1 per 4 cands)
        }
    }
    int cnt = (soff - soff0) / QPB;   // exact unless clamped (cnt == SLOTSH)

    // ---- Overflow fallback (>= SLOTSH survivors, rare): exact top-16 rescan ----
    if (cnt >= SLOTSH) {
        float rdF[16]; int riF[16];
#pragma unroll
        for (int t = 0; t < 16; ++t) { rdF[t] = FLTMAX; riF[t] = 0; }
        for (int mm = mstart; mm < mstart + HALF; ++mm) {
            float d = dists(xs[mm], ys[mm], zs[mm], ss[mm], xq, yq, zq, sq);
            pins(rdF, riF, d, mm);
        }
#pragma unroll
        for (int t = 0; t < 16; ++t)
            si[soff0 + t * QPB] = (unsigned short)riF[t];
        cnt = 16;
    }
    scnt[tid] = cnt;
    __syncthreads();

    // ---- Exact selection over both halves' survivors (threads 0..127) ----
    float rd[16]; int ri[16];
    if (tid < QPB) {
#pragma unroll
        for (int t = 0; t < 16; ++t) { rd[t] = FLTMAX; ri[t] = 0; }
        const int c1 = scnt[tid];
        for (int s = 0; s < c1; ++s) {
            int ii = (int)si[s * QPB + tid];
            float d = dists(xs[ii], ys[ii], zs[ii], ss[ii], xq, yq, zq, sq);
            pins(rd, ri, d, ii);
        }
        const int c2 = scnt[QPB + tid];
        for (int s = 0; s < c2; ++s) {
            int ii = (int)si[(ROWSH + s) * QPB + tid];
            float d = dists(xs[ii], ys[ii], zs[ii], ss[ii], xq, yq, zq, sq);
            pins(rd, ri, d, ii);
        }
        // hand off sorted indices to the upper-half partner thread
#pragma unroll
        for (int t = 0; t < 16; ++t)
            si[t * QPB + tid] = (unsigned short)ri[t];
    }
    __syncthreads();

    // ---- Emit edge features: out[b][c][q][k]; channels split across halves ----
    const size_t base = (((size_t)b * 6) * NN + q) * KK;
    if (tid < QPB) {
        float cvals[3] = {xq, yq, zq};
#pragma unroll
        for (int c = 0; c < 3; ++c) {
            float4 vv = make_float4(cvals[c], cvals[c], cvals[c], cvals[c]);
            float4* op = (float4*)(out + base + (size_t)c * NN * KK);
            op[0] = vv; op[1] = vv; op[2] = vv; op[3] = vv;
        }
        float nx[16];
#pragma unroll
        for (int k = 0; k < 16; ++k) nx[k] = xs[ri[k]] - xq;
        float4* op = (float4*)(out + base + (size_t)3 * NN * KK);
        op[0] = make_float4(nx[0], nx[1], nx[2], nx[3]);
        op[1] = make_float4(nx[4], nx[5], nx[6], nx[7]);
        op[2] = make_float4(nx[8], nx[9], nx[10], nx[11]);
        op[3] = make_float4(nx[12], nx[13], nx[14], nx[15]);
    } else {
        int rr[16];
#pragma unroll
        for (int k = 0; k < 16; ++k) rr[k] = (int)si[k * QPB + qc];
        float ny[16], nz[16];
#pragma unroll
        for (int k = 0; k < 16; ++k) {
            ny[k] = ys[rr[k]] - yq;
            nz[k] = zs[rr[k]] - zq;
        }
        float4* op = (float4*)(out + base + (size_t)4 * NN * KK);
        op[0] = make_float4(ny[0], ny[1], ny[2], ny[3]);
        op[1] = make_float4(ny[4], ny[5], ny[6], ny[7]);
        op[2] = make_float4(ny[8], ny[9], ny[10], ny[11]);
        op[3] = make_float4(ny[12], ny[13], ny[14], ny[15]);
        op = (float4*)(out + base + (size_t)5 * NN * KK);
        op[0] = make_float4(nz[0], nz[1], nz[2], nz[3]);
        op[1] = make_float4(nz[4], nz[5], nz[6], nz[7]);
        op[2] = make_float4(nz[8], nz[9], nz[10], nz[11]);
        op[3] = make_float4(nz[12], nz[13], nz[14], nz[15]);
    }
}

extern "C" void kernel_launch(void* const* d_in, const int* in_sizes, int n_in,
                              void* d_out, int out_size) {
    const float* cloud = (const float*)d_in[0];
    float* out = (float*)d_out;

    cudaFuncSetAttribute(knn_edge_kernel,
                         cudaFuncAttributeMaxDynamicSharedMemorySize, SMEM_BYTES);

    dim3 grid(BB * (NN / QPB));   // 256 blocks
    dim3 block(THREADS);
    knn_edge_kernel<<<grid, block, SMEM_BYTES>>>(cloud, out);
}

// round 10
// speedup vs baseline: 2.0582x; 1.0243x over previous
#include <cuda_runtime.h>
#include <cstdint>

#define BB 8
#define NN 4096
#define HALF 2048
#define KK 16
#define THREADS 256
#define QPB 128          // queries per block
#define SLOTSH 35        // survivor capacity before fallback (clamp row)
#define ROWSH 40         // physical rows per half (pads absorb pre-clamp overshoot)
#define FLTMAX 3.402823466e38f

// smem: m2x,m2y,m2z,ss (64KB) + si u16[2*ROWSH][128] (20KB) + scnt (1KB)
#define SMEM_BYTES ((4 * NN) * 4 + (2 * ROWSH * QPB) * 2 + THREADS * 4)

// ---------------- packed f32x2 helpers ----------------
__device__ __forceinline__ unsigned long long pk2(float v) {
    unsigned long long r;
    asm("mov.b64 %0, {%1, %1};" : "=l"(r) : "f"(v));
    return r;
}
__device__ __forceinline__ unsigned long long fma2_(unsigned long long a, unsigned long long b,
                                                    unsigned long long c) {
    unsigned long long r;
    asm("fma.rn.f32x2 %0, %1, %2, %3;" : "=l"(r) : "l"(a), "l"(b), "l"(c));
    return r;
}
__device__ __forceinline__ void unpk2(unsigned long long v, float& lo, float& hi) {
    asm("mov.b64 {%0, %1}, %2;" : "=f"(lo), "=f"(hi) : "l"(v));
}

// Rank-equivalent distance, 3 packed FMAs per 2 candidates.
// smem holds m2* = -2*coord and s = |p|^2; d' = s + (-2x)xq + (-2y)yq + (-2z)zq
//   (exact-math d = d' + sq, monotone => identical top-k per query)
__device__ __forceinline__ unsigned long long dist2p(
    unsigned long long x2, unsigned long long y2, unsigned long long z2, unsigned long long s2,
    unsigned long long xq2, unsigned long long yq2, unsigned long long zq2) {
    return fma2_(z2, zq2, fma2_(y2, yq2, fma2_(x2, xq2, s2)));
}

// Scalar version, bitwise-identical to dist2p lanes (.rn IEEE both paths).
__device__ __forceinline__ float dists(float m2x, float m2y, float m2z, float sm,
                                       float xq, float yq, float zq) {
    return fmaf(m2z, zq, fmaf(m2y, yq, fmaf(m2x, xq, sm)));
}

// Values-only sorted-16 insert (branch-free min/max shift)
__device__ __forceinline__ void insert16(float v[16], float d) {
#pragma unroll
    for (int j = 15; j >= 1; --j)
        v[j] = fminf(v[j], fmaxf(v[j - 1], d));
    v[0] = fminf(v[0], d);
}

// (d, idx) lexicographic pair-insert into sorted 16-list (lax.top_k order)
__device__ __forceinline__ void pins(float rd[16], int ri[16], float d, int i) {
    bool lessLast = (d < rd[15]) || (d == rd[15] && i < ri[15]);
    if (!lessLast) return;
#pragma unroll
    for (int j = 15; j >= 1; --j) {
        bool le = (d < rd[j - 1]) || (d == rd[j - 1] && i < ri[j - 1]);
        bool lj = (d < rd[j]) || (d == rd[j] && i < ri[j]);
        rd[j] = le ? rd[j - 1] : (lj ? d : rd[j]);
        ri[j] = le ? ri[j - 1] : (lj ? i : ri[j]);
    }
    bool l0 = (d < rd[0]) || (d == rd[0] && i < ri[0]);
    if (l0) { rd[0] = d; ri[0] = i; }
}

extern __shared__ char smem_raw[];

__global__ void __launch_bounds__(THREADS, 2)
knn_edge_kernel(const float* __restrict__ cloud, float* __restrict__ out) {
    float* xs = (float*)smem_raw;          // holds -2*x after prologue
    float* ys = xs + NN;                   // -2*y
    float* zs = ys + NN;                   // -2*z
    float* ss = zs + NN;                   // |p|^2 (from original coords)
    unsigned short* si = (unsigned short*)(ss + NN);   // [2*ROWSH][QPB]
    int* scnt = (int*)(si + 2 * ROWSH * QPB);          // [THREADS]

    const int tid = threadIdx.x;
    const int qc  = tid & (QPB - 1);
    const int h   = tid >> 7;          // half 0/1
    const int b    = blockIdx.x >> 5;
    const int tile = blockIdx.x & 31;
    const int q    = tile * QPB + qc;

    // ---- Load batch cloud to SMEM (SoA), compute norms, scale coords by -2 ----
    const float4* cb4 = (const float4*)(cloud + (size_t)b * 3 * NN);
    float4* xs4 = (float4*)xs; float4* ys4 = (float4*)ys;
    float4* zs4 = (float4*)zs; float4* ss4 = (float4*)ss;
    for (int i = tid; i < NN / 4; i += THREADS) {
        xs4[i] = cb4[i];
        ys4[i] = cb4[NN / 4 + i];
        zs4[i] = cb4[2 * (NN / 4) + i];
    }
    __syncthreads();
    for (int i = tid; i < NN / 4; i += THREADS) {
        float4 X = xs4[i], Y = ys4[i], Z = zs4[i], S;
        S.x = fmaf(X.x, X.x, fmaf(Y.x, Y.x, Z.x * Z.x));
        S.y = fmaf(X.y, X.y, fmaf(Y.y, Y.y, Z.y * Z.y));
        S.z = fmaf(X.z, X.z, fmaf(Y.z, Y.z, Z.z * Z.z));
        S.w = fmaf(X.w, X.w, fmaf(Y.w, Y.w, Z.w * Z.w));
        ss4[i] = S;
        xs4[i] = make_float4(-2.0f * X.x, -2.0f * X.y, -2.0f * X.z, -2.0f * X.w);
        ys4[i] = make_float4(-2.0f * Y.x, -2.0f * Y.y, -2.0f * Y.z, -2.0f * Y.w);
        zs4[i] = make_float4(-2.0f * Z.x, -2.0f * Z.y, -2.0f * Z.z, -2.0f * Z.w);
    }
    __syncthreads();

    // Original query coords (exact recovery: -0.5 * (-2x))
    const float xq = -0.5f * xs[q], yq = -0.5f * ys[q], zq = -0.5f * zs[q];
    const unsigned long long xq2 = pk2(xq), yq2 = pk2(yq), zq2 = pk2(zq);

    const ulonglong2* xs2 = (const ulonglong2*)xs;
    const ulonglong2* ys2 = (const ulonglong2*)ys;
    const ulonglong2* zs2 = (const ulonglong2*)zs;
    const ulonglong2* ss2 = (const ulonglong2*)ss;

    const int mstart = h * HALF;

    // ---- Pass 1: branch-free 16-bucket depth-2 min sketch over this half ----
    float m1[16], m2[16];
#pragma unroll
    for (int t = 0; t < 16; ++t) { m1[t] = FLTMAX; m2[t] = FLTMAX; }

#pragma unroll 1
    for (int it = 0; it < HALF / 16; ++it) {
        const int p0 = (mstart >> 2) + it * 4;
#pragma unroll
        for (int j = 0; j < 4; ++j) {
            ulonglong2 X = xs2[p0 + j], Y = ys2[p0 + j], Z = zs2[p0 + j], S = ss2[p0 + j];
            float d0, d1, d2v, d3;
            unpk2(dist2p(X.x, Y.x, Z.x, S.x, xq2, yq2, zq2), d0, d1);
            unpk2(dist2p(X.y, Y.y, Z.y, S.y, xq2, yq2, zq2), d2v, d3);
            const int t0 = j * 4;
            m2[t0 + 0] = fminf(m2[t0 + 0], fmaxf(m1[t0 + 0], d0)); m1[t0 + 0] = fminf(m1[t0 + 0], d0);
            m2[t0 + 1] = fminf(m2[t0 + 1], fmaxf(m1[t0 + 1], d1)); m1[t0 + 1] = fminf(m1[t0 + 1], d1);
            m2[t0 + 2] = fminf(m2[t0 + 2], fmaxf(m1[t0 + 2], d2v)); m1[t0 + 2] = fminf(m1[t0 + 2], d2v);
            m2[t0 + 3] = fminf(m2[t0 + 3], fmaxf(m1[t0 + 3], d3)); m1[t0 + 3] = fminf(m1[t0 + 3], d3);
        }
    }

    // T = 16th smallest of the 32 stored sketch values (>= exact d16 of this half)
    float v[16];
#pragma unroll
    for (int t = 0; t < 16; ++t) v[t] = FLTMAX;
#pragma unroll
    for (int t = 0; t < 16; ++t) { insert16(v, m1[t]); insert16(v, m2[t]); }
    const float T = v[15];

    // ---- Pass 2: collect indices of all d <= T via predicated offset walk ----
    const int soff0 = (h * ROWSH) * QPB + qc;
    const int somax = soff0 + SLOTSH * QPB;      // clamp row; pad rows absorb overshoot
    int soff = soff0;
#pragma unroll 1
    for (int it = 0; it < HALF / 16; ++it) {
        const int c0 = mstart + it * 16;
        const int p0 = c0 >> 2;
#pragma unroll
        for (int j = 0; j < 4; ++j) {
            ulonglong2 X = xs2[p0 + j], Y = ys2[p0 + j], Z = zs2[p0 + j], S = ss2[p0 + j];
            float dd[4];
            unpk2(dist2p(X.x, Y.x, Z.x, S.x, xq2, yq2, zq2), dd[0], dd[1]);
            unpk2(dist2p(X.y, Y.y, Z.y, S.y, xq2, yq2, zq2), dd[2], dd[3]);
#pragma unroll
            for (int k = 0; k < 4; ++k) {
                bool pr = (dd[k] <= T);
                if (pr) si[soff] = (unsigned short)(c0 + j * 4 + k);
                if (pr) soff += QPB;
            }
            soff = (soff > somax) ? somax : soff;   // amortized clamp (1 per 4 cands)
        }
    }
    int cnt = (soff - soff0) / QPB;   // exact unless clamped (cnt == SLOTSH)

    // ---- Overflow fallback (>= SLOTSH survivors, rare): exact top-16 rescan ----
    if (cnt >= SLOTSH) {
        float rdF[16]; int riF[16];
#pragma unroll
        for (int t = 0; t < 16; ++t) { rdF[t] = FLTMAX; riF[t] = 0; }
        for (int mm = mstart; mm < mstart + HALF; ++mm) {
            float d = dists(xs[mm], ys[mm], zs[mm], ss[mm], xq, yq, zq);
            pins(rdF, riF, d, mm);
        }
#pragma unroll
        for (int t = 0; t < 16; ++t)
            si[soff0 + t * QPB] = (unsigned short)riF[t];
        cnt = 16;
    }
    scnt[tid] = cnt;
    __syncthreads();

    // ---- Exact selection over both halves' survivors (threads 0..127) ----
    float rd[16]; int ri[16];
    if (tid < QPB) {
#pragma unroll
        for (int t = 0; t < 16; ++t) { rd[t] = FLTMAX; ri[t] = 0; }
        const int c1 = scnt[tid];
        for (int s = 0; s < c1; ++s) {
            int ii = (int)si[s * QPB + tid];
            float d = dists(xs[ii], ys[ii], zs[ii], ss[ii], xq, yq, zq);
            pins(rd, ri, d, ii);
        }
        const int c2 = scnt[QPB + tid];
        for (int s = 0; s < c2; ++s) {
            int ii = (int)si[(ROWSH + s) * QPB + tid];
            float d = dists(xs[ii], ys[ii], zs[ii], ss[ii], xq, yq, zq);
            pins(rd, ri, d, ii);
        }
        // hand off sorted indices to the upper-half partner thread
#pragma unroll
        for (int t = 0; t < 16; ++t)
            si[t * QPB + tid] = (unsigned short)ri[t];
    }
    __syncthreads();

    // ---- Emit edge features: out[b][c][q][k]; channels split across halves ----
    // Recover exact original coords: x = -0.5 * (-2x)
    const size_t base = (((size_t)b * 6) * NN + q) * KK;
    if (tid < QPB) {
        float cvals[3] = {xq, yq, zq};
#pragma unroll
        for (int c = 0; c < 3; ++c) {
            float4 vv = make_float4(cvals[c], cvals[c], cvals[c], cvals[c]);
            float4* op = (float4*)(out + base + (size_t)c * NN * KK);
            op[0] = vv; op[1] = vv; op[2] = vv; op[3] = vv;
        }
        float nx[16];
#pragma unroll
        for (int k = 0; k < 16; ++k) {
            float xn = -0.5f * xs[ri[k]];
            nx[k] = xn - xq;
        }
        float4* op = (float4*)(out + base + (size_t)3 * NN * KK);
        op[0] = make_float4(nx[0], nx[1], nx[2], nx[3]);
        op[1] = make_float4(nx[4], nx[5], nx[6], nx[7]);
        op[2] = make_float4(nx[8], nx[9], nx[10], nx[11]);
        op[3] = make_float4(nx[12], nx[13], nx[14], nx[15]);
    } else {
        int rr[16];
#pragma unroll
        for (int k = 0; k < 16; ++k) rr[k] = (int)si[k * QPB + qc];
        float ny[16], nz[16];
#pragma unroll
        for (int k = 0; k < 16; ++k) {
            float yn = -0.5f * ys[rr[k]];
            float zn = -0.5f * zs[rr[k]];
            ny[k] = yn - yq;
            nz[k] = zn - zq;
        }
        float4* op = (float4*)(out + base + (size_t)4 * NN * KK);
        op[0] = make_float4(ny[0], ny[1], ny[2], ny[3]);
        op[1] = make_float4(ny[4], ny[5], ny[6], ny[7]);
        op[2] = make_float4(ny[8], ny[9], ny[10], ny[11]);
        op[3] = make_float4(ny[12], ny[13], ny[14], ny[15]);
        op = (float4*)(out + base + (size_t)5 * NN * KK);
        op[0] = make_float4(nz[0], nz[1], nz[2], nz[3]);
        op[1] = make_float4(nz[4], nz[5], nz[6], nz[7]);
        op[2] = make_float4(nz[8], nz[9], nz[10], nz[11]);
        op[3] = make_float4(nz[12], nz[13], nz[14], nz[15]);
    }
}

extern "C" void kernel_launch(void* const* d_in, const int* in_sizes, int n_in,
                              void* d_out, int out_size) {
    const float* cloud = (const float*)d_in[0];
    float* out = (float*)d_out;

    cudaFuncSetAttribute(knn_edge_kernel,
                         cudaFuncAttributeMaxDynamicSharedMemorySize, SMEM_BYTES);

    dim3 grid(BB * (NN / QPB));   // 256 blocks
    dim3 block(THREADS);
    knn_edge_kernel<<<grid, block, SMEM_BYTES>>>(cloud, out);
}